// round 9
// baseline (speedup 1.0000x reference)
#include <cuda_runtime.h>
#include <cuda_fp16.h>
#include <cstdint>
#include <cstddef>

// ---------------- problem constants ----------------
constexpr int NB     = 1024;   // batches
constexpr int NQC    = 32;     // queries per batch
constexpr int NDOC   = 2048;   // docs per batch
constexpr int DK     = 128;    // embedding dim
constexpr int NHALF  = 2;      // doc-range splits per batch
constexpr int HDOC   = NDOC / NHALF;   // 1024 docs per CTA
constexpr int TILE_M = 64;     // docs per tile (8 per warp)
constexpr int NTILES = HDOC / TILE_M;  // 16
constexpr int PITCH  = 272;    // fp16 B row pitch
constexpr int SPITCH = 544;    // f32 stage row pitch (512 + 32 pad)
constexpr int NW     = 8;      // warps per CTA
constexpr int NT     = NW * 32;  // 256 threads
constexpr int NSTG   = 3;      // pipeline depth

// ---------------- smem layout (bytes, dynamic) ----------------
constexpr int SM_B     = 0;                        // fp16 queries 32 x PITCH = 8704
constexpr int SM_RED   = NQC * PITCH;              // 8704: 256 f32 reduce scratch
constexpr int SM_STAGE = SM_RED + NT * 4;          // 9728
constexpr int STAGE_B  = TILE_M * SPITCH;          // 34816 per buffer
constexpr int SMEM_TOTAL = SM_STAGE + NSTG * STAGE_B;  // 114176 (x2 CTAs/SM)

// per-(batch,half) partial maxima [NB*NHALF, NQC]; fully rewritten each run
__device__ float g_part[(size_t)NB * NHALF * NQC];

// ---------------- PTX helpers ----------------
__device__ __forceinline__ uint32_t smem_u32(const void* p) {
    uint32_t a;
    asm("{ .reg .u64 t; cvta.to.shared.u64 t, %1; cvt.u32.u64 %0, t; }" : "=r"(a) : "l"(p));
    return a;
}
__device__ __forceinline__ uint32_t pack_h2(float lo, float hi) {
    uint32_t r;
    asm("cvt.rn.f16x2.f32 %0, %1, %2;" : "=r"(r) : "f"(hi), "f"(lo));
    return r;
}
__device__ __forceinline__ uint32_t lds32(uint32_t a) {
    uint32_t v;
    asm volatile("ld.shared.b32 %0, [%1];" : "=r"(v) : "r"(a));
    return v;
}
__device__ __forceinline__ float2 lds_v2(uint32_t a) {
    float2 v;
    asm volatile("ld.shared.v2.f32 {%0,%1}, [%2];" : "=f"(v.x), "=f"(v.y) : "r"(a));
    return v;
}
__device__ __forceinline__ void sts64(uint32_t a, uint32_t r0, uint32_t r1) {
    asm volatile("st.shared.v2.b32 [%0], {%1,%2};" :: "r"(a), "r"(r0), "r"(r1) : "memory");
}
__device__ __forceinline__ void cp_async16(uint32_t sa, const void* g) {
    asm volatile("cp.async.cg.shared.global [%0], [%1], 16;" :: "r"(sa), "l"(g));
}
__device__ __forceinline__ void cp_commit() { asm volatile("cp.async.commit_group;" ::: "memory"); }
__device__ __forceinline__ void cp_wait2()  { asm volatile("cp.async.wait_group 2;" ::: "memory"); }
__device__ __forceinline__ void mma16816(float* c, const uint32_t* a, const uint32_t* b) {
    asm volatile(
        "mma.sync.aligned.m16n8k16.row.col.f32.f16.f16.f32 "
        "{%0,%1,%2,%3}, {%4,%5,%6,%7}, {%8,%9}, {%0,%1,%2,%3};"
        : "+f"(c[0]), "+f"(c[1]), "+f"(c[2]), "+f"(c[3])
        : "r"(a[0]), "r"(a[1]), "r"(a[2]), "r"(a[3]), "r"(b[0]), "r"(b[1]));
}

// ---------------- phase 1: qnorm + streaming MaxSim over a half-batch ----------------
__global__ void __launch_bounds__(NT, 2)
maxsim_kernel(const float* __restrict__ q, const float* __restrict__ doc) {
    extern __shared__ char smem[];
    const int b    = blockIdx.x >> 1;       // batch
    const int h    = blockIdx.x & 1;        // doc-range half
    const int tid  = threadIdx.x;
    const int w    = tid >> 5;               // warp 0..7, owns doc rows [w*8, w*8+8)
    const int lane = tid & 31;

    const uint32_t sb  = smem_u32(smem);
    const uint32_t smB = sb + SM_B;
    const uint32_t smS = sb + SM_STAGE;
    float* red = reinterpret_cast<float*>(smem + SM_RED);

    const char* dbase = reinterpret_cast<const char*>(doc) +
                        ((size_t)b * NDOC + (size_t)h * HDOC) * DK * 4;
    // warp's cp.async offsets: thread writes rows w*8+r at byte col lane*16
    const uint32_t s_w_base = (w * 8) * SPITCH + lane * 16;
    const size_t   g_w_base = (size_t)(w * 8) * 512 + lane * 16;
    // thread's fragment-read base: row w*8+(lane>>2), byte col (lane&3)*8
    const uint32_t s_r_base = (w * 8 + (lane >> 2)) * SPITCH + (lane & 3) * 8;

    // --- prologue FIRST: get tiles 0..2 in flight before query math ---
    #pragma unroll
    for (int p = 0; p < NSTG; p++) {
        const char* g = dbase + (size_t)p * TILE_M * 512 + g_w_base;
        uint32_t sdst = smS + p * STAGE_B + s_w_base;
        #pragma unroll
        for (int r = 0; r < 8; r++)
            cp_async16(sdst + r * SPITCH, g + r * 512);
        cp_commit();
    }

    // --- normalize this batch's 32 queries -> fp16 smB (warp w does rows w*4..w*4+3) ---
    {
        const float* qb = q + (size_t)b * NQC * DK;
        #pragma unroll
        for (int i = 0; i < 4; i++) {
            int r = w * 4 + i;
            float4 v = reinterpret_cast<const float4*>(qb + (size_t)r * DK)[lane];
            float ss = v.x * v.x + v.y * v.y + v.z * v.z + v.w * v.w;
            #pragma unroll
            for (int o = 16; o; o >>= 1) ss += __shfl_xor_sync(0xFFFFFFFFu, ss, o);
            float rn = rsqrtf(fmaxf(ss, 1e-24f));
            sts64(smB + r * PITCH + lane * 8,
                  pack_h2(v.x * rn, v.y * rn), pack_h2(v.z * rn, v.w * rn));
        }
    }
    __syncthreads();

    // --- preload ALL B fragments into registers (64 regs): no B LDS in the loop ---
    uint32_t bf[8][4][2];
    #pragma unroll
    for (int kb = 0; kb < 8; kb++)
        #pragma unroll
        for (int n = 0; n < 4; n++) {
            uint32_t ba = smB + (n * 8 + (lane >> 2)) * PITCH + kb * 32 + (lane & 3) * 4;
            bf[kb][n][0] = lds32(ba);
            bf[kb][n][1] = lds32(ba + 16);
        }

    float vmax[8];
    #pragma unroll
    for (int e = 0; e < 8; e++) vmax[e] = -1e30f;

    for (int t = 0; t < NTILES; t++) {
        cp_wait2();      // tile t's group complete (<=2 newer pending)
        __syncwarp();    // warp-wide visibility of warp's rows

        const uint32_t buf = (uint32_t)(t % NSTG) * STAGE_B;
        const uint32_t trd = smS + buf + s_r_base;

        // --- read fragment elements straight from f32 stage; convert in registers ---
        uint32_t af0[8], af1[8];
        float ss = 0.f;
        #pragma unroll
        for (int kb = 0; kb < 8; kb++) {
            float2 p0 = lds_v2(trd + kb * 64);
            float2 p1 = lds_v2(trd + kb * 64 + 32);
            ss += p0.x * p0.x + p0.y * p0.y + p1.x * p1.x + p1.y * p1.y;
            af0[kb] = pack_h2(p0.x, p0.y);
            af1[kb] = pack_h2(p1.x, p1.y);
        }
        // row norm: 4 lanes (same lane>>2) hold disjoint 32-col partials
        ss += __shfl_xor_sync(0xFFFFFFFFu, ss, 1);
        ss += __shfl_xor_sync(0xFFFFFFFFu, ss, 2);
        const float rn = rsqrtf(fmaxf(ss, 1e-24f));

        __syncwarp();    // all lanes done reading buf before overwrite
        if (t + NSTG < NTILES) {
            const char* g = dbase + (size_t)(t + NSTG) * TILE_M * 512 + g_w_base;
            uint32_t sdst = smS + buf + s_w_base;
            #pragma unroll
            for (int r = 0; r < 8; r++)
                cp_async16(sdst + r * SPITCH, g + r * 512);
        }
        cp_commit();     // unconditional: uniform wait accounting

        // --- HMMA: 8 real doc rows x 32 queries (upper fragment half duplicated) ---
        float acc[4][4];
        #pragma unroll
        for (int n = 0; n < 4; n++)
            #pragma unroll
            for (int i = 0; i < 4; i++) acc[n][i] = 0.f;

        #pragma unroll
        for (int kb = 0; kb < 8; kb++) {
            uint32_t aa[4] = {af0[kb], af0[kb], af1[kb], af1[kb]};
            #pragma unroll
            for (int n = 0; n < 4; n++) mma16816(acc[n], aa, bf[kb][n]);
        }

        // --- epilogue: c0,c1 are this thread's row; scale by 1/||d||, running max ---
        #pragma unroll
        for (int n = 0; n < 4; n++) {
            vmax[n * 2 + 0] = fmaxf(vmax[n * 2 + 0], acc[n][0] * rn);
            vmax[n * 2 + 1] = fmaxf(vmax[n * 2 + 1], acc[n][1] * rn);
        }
    }

    // ---- reduce: max over lanes sharing a query column (xor 4,8,16) ----
    #pragma unroll
    for (int e = 0; e < 8; e++) {
        vmax[e] = fmaxf(vmax[e], __shfl_xor_sync(0xFFFFFFFFu, vmax[e], 4));
        vmax[e] = fmaxf(vmax[e], __shfl_xor_sync(0xFFFFFFFFu, vmax[e], 8));
        vmax[e] = fmaxf(vmax[e], __shfl_xor_sync(0xFFFFFFFFu, vmax[e], 16));
    }
    if (lane < 4) {
        #pragma unroll
        for (int e = 0; e < 8; e++) {
            int col = (e >> 1) * 8 + lane * 2 + (e & 1);
            red[w * 32 + col] = vmax[e];
        }
    }
    __syncthreads();
    if (tid < 32) {
        float m = red[tid];
        #pragma unroll
        for (int ww = 1; ww < NW; ww++) m = fmaxf(m, red[ww * 32 + tid]);
        g_part[(size_t)blockIdx.x * NQC + tid] = m;   // partial max for (b, h)
    }
}

// ---------------- phase 2: combine halves (max) and sum queries ----------------
__global__ void __launch_bounds__(256) combine_kernel(float* __restrict__ out) {
    const int b    = blockIdx.x * 8 + (threadIdx.x >> 5);  // one warp per batch
    const int lane = threadIdx.x & 31;
    float m = fmaxf(g_part[(size_t)(b * 2 + 0) * NQC + lane],
                    g_part[(size_t)(b * 2 + 1) * NQC + lane]);
    #pragma unroll
    for (int o = 16; o; o >>= 1) m += __shfl_xor_sync(0xFFFFFFFFu, m, o);
    if (lane == 0) out[b] = m;
}

// ---------------- host launch ----------------
extern "C" void kernel_launch(void* const* d_in, const int* in_sizes, int n_in,
                              void* d_out, int out_size) {
    const float* q   = (const float*)d_in[0];   // [1024, 32, 128] f32
    const float* doc = (const float*)d_in[1];   // [1024, 2048, 128] f32
    float* out = (float*)d_out;                 // [1024] f32

    cudaFuncSetAttribute(maxsim_kernel,
                         cudaFuncAttributeMaxDynamicSharedMemorySize, SMEM_TOTAL);

    maxsim_kernel<<<NB * NHALF, NT, SMEM_TOTAL>>>(q, doc);
    combine_kernel<<<NB / 8, 256>>>(out);
}

// round 10
// speedup vs baseline: 1.0296x; 1.0296x over previous
#include <cuda_runtime.h>
#include <cuda_fp16.h>
#include <cstdint>
#include <cstddef>

// ---------------- problem constants ----------------
constexpr int NB     = 1024;   // batches
constexpr int NQC    = 32;     // queries per batch
constexpr int NDOC   = 2048;   // docs per batch
constexpr int DK     = 128;    // embedding dim
constexpr int TILE_M = 64;     // docs per tile (8 per warp)
constexpr int NTILES = NDOC / TILE_M;  // 32
constexpr int PITCH  = 272;    // fp16 B row pitch
constexpr int SPITCH = 544;    // f32 stage row pitch (512 + 32 pad)
constexpr int NW     = 8;      // warps per CTA
constexpr int NT     = NW * 32;  // 256 threads
constexpr int NSTG   = 3;      // ring buffers (prefetch distance 2)

// ---------------- smem layout (bytes, dynamic) ----------------
constexpr int SM_B     = 0;                        // fp16 queries 32 x PITCH = 8704
constexpr int SM_RED   = NQC * PITCH;              // 8704: 256 f32 reduce scratch
constexpr int SM_STAGE = SM_RED + NT * 4;          // 9728
constexpr int STAGE_B  = TILE_M * SPITCH;          // 34816 per buffer
constexpr int SMEM_TOTAL = SM_STAGE + NSTG * STAGE_B;  // 114176 (x2 CTAs/SM)

// ---------------- PTX helpers ----------------
__device__ __forceinline__ uint32_t smem_u32(const void* p) {
    uint32_t a;
    asm("{ .reg .u64 t; cvta.to.shared.u64 t, %1; cvt.u32.u64 %0, t; }" : "=r"(a) : "l"(p));
    return a;
}
__device__ __forceinline__ uint32_t pack_h2(float lo, float hi) {
    uint32_t r;
    asm("cvt.rn.f16x2.f32 %0, %1, %2;" : "=r"(r) : "f"(hi), "f"(lo));
    return r;
}
__device__ __forceinline__ uint32_t lds32(uint32_t a) {
    uint32_t v;
    asm volatile("ld.shared.b32 %0, [%1];" : "=r"(v) : "r"(a));
    return v;
}
__device__ __forceinline__ float2 lds_v2(uint32_t a) {
    float2 v;
    asm volatile("ld.shared.v2.f32 {%0,%1}, [%2];" : "=f"(v.x), "=f"(v.y) : "r"(a));
    return v;
}
__device__ __forceinline__ void sts64(uint32_t a, uint32_t r0, uint32_t r1) {
    asm volatile("st.shared.v2.b32 [%0], {%1,%2};" :: "r"(a), "r"(r0), "r"(r1) : "memory");
}
__device__ __forceinline__ void cp_async16(uint32_t sa, const void* g) {
    asm volatile("cp.async.cg.shared.global [%0], [%1], 16;" :: "r"(sa), "l"(g));
}
__device__ __forceinline__ void cp_commit() { asm volatile("cp.async.commit_group;" ::: "memory"); }
__device__ __forceinline__ void cp_wait2()  { asm volatile("cp.async.wait_group 2;" ::: "memory"); }
__device__ __forceinline__ void mma16816(float* c, const uint32_t* a, const uint32_t* b) {
    asm volatile(
        "mma.sync.aligned.m16n8k16.row.col.f32.f16.f16.f32 "
        "{%0,%1,%2,%3}, {%4,%5,%6,%7}, {%8,%9}, {%0,%1,%2,%3};"
        : "+f"(c[0]), "+f"(c[1]), "+f"(c[2]), "+f"(c[3])
        : "r"(a[0]), "r"(a[1]), "r"(a[2]), "r"(a[3]), "r"(b[0]), "r"(b[1]));
}

// ---------------- fused kernel: qnorm + streaming MaxSim ----------------
__global__ void __launch_bounds__(NT, 2)
maxsim_kernel(const float* __restrict__ q, const float* __restrict__ doc,
              float* __restrict__ out) {
    extern __shared__ char smem[];
    const int b    = blockIdx.x;
    const int tid  = threadIdx.x;
    const int w    = tid >> 5;      // warp 0..7, owns doc rows [w*8, w*8+8) of each tile
    const int lane = tid & 31;

    const uint32_t sb  = smem_u32(smem);
    const uint32_t smB = sb + SM_B;
    const uint32_t smS = sb + SM_STAGE;
    float* red = reinterpret_cast<float*>(smem + SM_RED);

    const char* dbase = reinterpret_cast<const char*>(doc) + (size_t)b * NDOC * DK * 4;
    // warp's cp.async offsets: thread writes rows w*8+r at byte col lane*16
    const uint32_t s_w_base = (w * 8) * SPITCH + lane * 16;
    const size_t   g_w_base = (size_t)(w * 8) * 512 + lane * 16;
    // thread's fragment-read base: row w*8+(lane>>2), byte col (lane&3)*8
    const uint32_t s_r_base = (w * 8 + (lane >> 2)) * SPITCH + (lane & 3) * 8;

    // --- prologue: issue tiles 0,1 (prefetch distance 2 on a 3-buffer ring) ---
    #pragma unroll
    for (int p = 0; p < 2; p++) {
        const char* g = dbase + (size_t)p * TILE_M * 512 + g_w_base;
        uint32_t sdst = smS + (uint32_t)p * STAGE_B + s_w_base;
        #pragma unroll
        for (int r = 0; r < 8; r++)
            cp_async16(sdst + r * SPITCH, g + r * 512);
        cp_commit();
    }

    // --- normalize this batch's 32 queries -> fp16 smB (warp w does rows w*4..w*4+3) ---
    {
        const float* qb = q + (size_t)b * NQC * DK;
        #pragma unroll
        for (int i = 0; i < 4; i++) {
            int r = w * 4 + i;
            float4 v = reinterpret_cast<const float4*>(qb + (size_t)r * DK)[lane];
            float ss = v.x * v.x + v.y * v.y + v.z * v.z + v.w * v.w;
            #pragma unroll
            for (int o = 16; o; o >>= 1) ss += __shfl_xor_sync(0xFFFFFFFFu, ss, o);
            float rn = rsqrtf(fmaxf(ss, 1e-24f));
            sts64(smB + r * PITCH + lane * 8,
                  pack_h2(v.x * rn, v.y * rn), pack_h2(v.z * rn, v.w * rn));
        }
    }
    __syncthreads();

    // --- preload ALL B fragments into registers (64 regs): no B LDS in the loop ---
    uint32_t bf[8][4][2];
    #pragma unroll
    for (int kb = 0; kb < 8; kb++)
        #pragma unroll
        for (int n = 0; n < 4; n++) {
            uint32_t ba = smB + (n * 8 + (lane >> 2)) * PITCH + kb * 32 + (lane & 3) * 4;
            bf[kb][n][0] = lds32(ba);
            bf[kb][n][1] = lds32(ba + 16);
        }

    float vmax[8];
    #pragma unroll
    for (int e = 0; e < 8; e++) vmax[e] = -1e30f;

    for (int t = 0; t < NTILES; t++) {
        // --- FIRST: issue prefetch of tile t+2 into buffer (t+2)%3.
        //     That buffer was fully consumed at iteration t-1 (all lanes of this
        //     warp are past it), so no WAR and no syncwarp gate. DRAM issue
        //     stream never pauses on the convert chain below. ---
        if (t + 2 < NTILES) {
            const char* g = dbase + (size_t)(t + 2) * TILE_M * 512 + g_w_base;
            uint32_t sdst = smS + (uint32_t)((t + 2) % NSTG) * STAGE_B + s_w_base;
            #pragma unroll
            for (int r = 0; r < 8; r++)
                cp_async16(sdst + r * SPITCH, g + r * 512);
        }
        cp_commit();     // unconditional: uniform wait accounting

        cp_wait2();      // tile t's group retired (<=2 newer pending)
        __syncwarp();    // warp-wide visibility of warp's rows

        const uint32_t trd = smS + (uint32_t)(t % NSTG) * STAGE_B + s_r_base;

        // --- read fragment elements straight from f32 stage; convert in registers ---
        uint32_t af0[8], af1[8];
        float ss = 0.f;
        #pragma unroll
        for (int kb = 0; kb < 8; kb++) {
            float2 p0 = lds_v2(trd + kb * 64);
            float2 p1 = lds_v2(trd + kb * 64 + 32);
            ss += p0.x * p0.x + p0.y * p0.y + p1.x * p1.x + p1.y * p1.y;
            af0[kb] = pack_h2(p0.x, p0.y);
            af1[kb] = pack_h2(p1.x, p1.y);
        }
        // row norm: 4 lanes (same lane>>2) hold disjoint 32-col partials
        ss += __shfl_xor_sync(0xFFFFFFFFu, ss, 1);
        ss += __shfl_xor_sync(0xFFFFFFFFu, ss, 2);
        const float rn = rsqrtf(fmaxf(ss, 1e-24f));

        // --- HMMA: 8 real doc rows x 32 queries (upper fragment half duplicated) ---
        float acc[4][4];
        #pragma unroll
        for (int n = 0; n < 4; n++)
            #pragma unroll
            for (int i = 0; i < 4; i++) acc[n][i] = 0.f;

        #pragma unroll
        for (int kb = 0; kb < 8; kb++) {
            uint32_t aa[4] = {af0[kb], af0[kb], af1[kb], af1[kb]};
            #pragma unroll
            for (int n = 0; n < 4; n++) mma16816(acc[n], aa, bf[kb][n]);
        }

        // --- epilogue: c0,c1 are this thread's row; scale by 1/||d||, running max ---
        #pragma unroll
        for (int n = 0; n < 4; n++) {
            vmax[n * 2 + 0] = fmaxf(vmax[n * 2 + 0], acc[n][0] * rn);
            vmax[n * 2 + 1] = fmaxf(vmax[n * 2 + 1], acc[n][1] * rn);
        }
    }

    // ---- reduce: max over lanes sharing a query column (xor 4,8,16) ----
    #pragma unroll
    for (int e = 0; e < 8; e++) {
        vmax[e] = fmaxf(vmax[e], __shfl_xor_sync(0xFFFFFFFFu, vmax[e], 4));
        vmax[e] = fmaxf(vmax[e], __shfl_xor_sync(0xFFFFFFFFu, vmax[e], 8));
        vmax[e] = fmaxf(vmax[e], __shfl_xor_sync(0xFFFFFFFFu, vmax[e], 16));
    }
    if (lane < 4) {
        #pragma unroll
        for (int e = 0; e < 8; e++) {
            int col = (e >> 1) * 8 + lane * 2 + (e & 1);
            red[w * 32 + col] = vmax[e];
        }
    }
    __syncthreads();
    if (tid < 32) {
        float m = red[tid];
        #pragma unroll
        for (int ww = 1; ww < NW; ww++) m = fmaxf(m, red[ww * 32 + tid]);
        #pragma unroll
        for (int o = 16; o; o >>= 1) m += __shfl_xor_sync(0xFFFFFFFFu, m, o);
        if (tid == 0) out[b] = m;
    }
}

// ---------------- host launch ----------------
extern "C" void kernel_launch(void* const* d_in, const int* in_sizes, int n_in,
                              void* d_out, int out_size) {
    const float* q   = (const float*)d_in[0];   // [1024, 32, 128] f32
    const float* doc = (const float*)d_in[1];   // [1024, 2048, 128] f32
    float* out = (float*)d_out;                 // [1024] f32

    cudaFuncSetAttribute(maxsim_kernel,
                         cudaFuncAttributeMaxDynamicSharedMemorySize, SMEM_TOTAL);

    maxsim_kernel<<<NB, NT, SMEM_TOTAL>>>(q, doc, out);
}

// round 11
// speedup vs baseline: 1.0339x; 1.0042x over previous
#include <cuda_runtime.h>
#include <cuda_fp16.h>
#include <cstdint>
#include <cstddef>

// ---------------- problem constants ----------------
constexpr int NB     = 1024;   // batches
constexpr int NQC    = 32;     // queries per batch
constexpr int NDOC   = 2048;   // docs per batch
constexpr int DK     = 128;    // embedding dim
constexpr int TILE_M = 64;     // docs per tile (8 per warp)
constexpr int NTILES = NDOC / TILE_M;  // 32
constexpr int PITCH  = 272;    // fp16 B row pitch
constexpr int SPITCH = 544;    // f32 stage row pitch (512 + 32 pad)
constexpr int NW     = 8;      // warps per CTA
constexpr int NT     = NW * 32;  // 256 threads
constexpr int NSTG   = 3;      // ring buffers (prefetch distance 2)

// ---------------- smem layout (bytes, dynamic) ----------------
constexpr int SM_B     = 0;                        // fp16 queries 32 x PITCH = 8704
constexpr int SM_RED   = NQC * PITCH;              // 8704: 256 f32 reduce scratch
constexpr int SM_STAGE = SM_RED + NT * 4;          // 9728
constexpr int STAGE_B  = TILE_M * SPITCH;          // 34816 per buffer
constexpr int SMEM_TOTAL = SM_STAGE + NSTG * STAGE_B;  // 114176 (x2 CTAs/SM)

// ---------------- PTX helpers ----------------
__device__ __forceinline__ uint32_t smem_u32(const void* p) {
    uint32_t a;
    asm("{ .reg .u64 t; cvta.to.shared.u64 t, %1; cvt.u32.u64 %0, t; }" : "=r"(a) : "l"(p));
    return a;
}
__device__ __forceinline__ uint32_t pack_h2(float lo, float hi) {
    uint32_t r;
    asm("cvt.rn.f16x2.f32 %0, %1, %2;" : "=r"(r) : "f"(hi), "f"(lo));
    return r;
}
__device__ __forceinline__ uint32_t lds32(uint32_t a) {
    uint32_t v;
    asm volatile("ld.shared.b32 %0, [%1];" : "=r"(v) : "r"(a));
    return v;
}
__device__ __forceinline__ float2 lds_v2(uint32_t a) {
    float2 v;
    asm volatile("ld.shared.v2.f32 {%0,%1}, [%2];" : "=f"(v.x), "=f"(v.y) : "r"(a));
    return v;
}
__device__ __forceinline__ void sts64(uint32_t a, uint32_t r0, uint32_t r1) {
    asm volatile("st.shared.v2.b32 [%0], {%1,%2};" :: "r"(a), "r"(r0), "r"(r1) : "memory");
}
__device__ __forceinline__ void cp_async16(uint32_t sa, const void* g) {
    asm volatile("cp.async.cg.shared.global [%0], [%1], 16;" :: "r"(sa), "l"(g));
}
__device__ __forceinline__ void cp_commit() { asm volatile("cp.async.commit_group;" ::: "memory"); }
__device__ __forceinline__ void cp_wait2()  { asm volatile("cp.async.wait_group 2;" ::: "memory"); }
__device__ __forceinline__ void mma16816(float* c, const uint32_t* a, const uint32_t* b) {
    asm volatile(
        "mma.sync.aligned.m16n8k16.row.col.f32.f16.f16.f32 "
        "{%0,%1,%2,%3}, {%4,%5,%6,%7}, {%8,%9}, {%0,%1,%2,%3};"
        : "+f"(c[0]), "+f"(c[1]), "+f"(c[2]), "+f"(c[3])
        : "r"(a[0]), "r"(a[1]), "r"(a[2]), "r"(a[3]), "r"(b[0]), "r"(b[1]));
}

// ---------------- fused kernel: qnorm + streaming MaxSim ----------------
__global__ void __launch_bounds__(NT, 2)
maxsim_kernel(const float* __restrict__ q, const float* __restrict__ doc,
              float* __restrict__ out) {
    extern __shared__ char smem[];
    const int b    = blockIdx.x;
    const int tid  = threadIdx.x;
    const int w    = tid >> 5;      // warp 0..7, owns doc rows [w*8, w*8+8) of each tile
    const int lane = tid & 31;

    const uint32_t sb  = smem_u32(smem);
    const uint32_t smB = sb + SM_B;
    const uint32_t smS = sb + SM_STAGE;
    float* red = reinterpret_cast<float*>(smem + SM_RED);

    const char* dbase = reinterpret_cast<const char*>(doc) + (size_t)b * NDOC * DK * 4;
    // warp's cp.async offsets: thread writes rows w*8+r at byte col lane*16
    const uint32_t s_w_base = (w * 8) * SPITCH + lane * 16;
    const size_t   g_w_base = (size_t)(w * 8) * 512 + lane * 16;
    // thread's fragment-read base: row w*8+(lane>>2), byte col (lane&3)*8
    const uint32_t s_r_base = (w * 8 + (lane >> 2)) * SPITCH + (lane & 3) * 8;

    // --- prologue: issue tiles 0,1 (prefetch distance 2 on a 3-buffer ring) ---
    #pragma unroll
    for (int p = 0; p < 2; p++) {
        const char* g = dbase + (size_t)p * TILE_M * 512 + g_w_base;
        uint32_t sdst = smS + (uint32_t)p * STAGE_B + s_w_base;
        #pragma unroll
        for (int r = 0; r < 8; r++)
            cp_async16(sdst + r * SPITCH, g + r * 512);
        cp_commit();
    }

    // --- normalize this batch's 32 queries -> fp16 smB (warp w does rows w*4..w*4+3) ---
    {
        const float* qb = q + (size_t)b * NQC * DK;
        #pragma unroll
        for (int i = 0; i < 4; i++) {
            int r = w * 4 + i;
            float4 v = reinterpret_cast<const float4*>(qb + (size_t)r * DK)[lane];
            float ss = v.x * v.x + v.y * v.y + v.z * v.z + v.w * v.w;
            #pragma unroll
            for (int o = 16; o; o >>= 1) ss += __shfl_xor_sync(0xFFFFFFFFu, ss, o);
            float rn = rsqrtf(fmaxf(ss, 1e-24f));
            sts64(smB + r * PITCH + lane * 8,
                  pack_h2(v.x * rn, v.y * rn), pack_h2(v.z * rn, v.w * rn));
        }
    }
    __syncthreads();

    // --- preload ALL B fragments into registers (64 regs): no B LDS in the loop ---
    uint32_t bf[8][4][2];
    #pragma unroll
    for (int kb = 0; kb < 8; kb++)
        #pragma unroll
        for (int n = 0; n < 4; n++) {
            uint32_t ba = smB + (n * 8 + (lane >> 2)) * PITCH + kb * 32 + (lane & 3) * 4;
            bf[kb][n][0] = lds32(ba);
            bf[kb][n][1] = lds32(ba + 16);
        }

    float vmax[8];
    #pragma unroll
    for (int e = 0; e < 8; e++) vmax[e] = -1e30f;

    for (int t = 0; t < NTILES; t++) {
        // --- FIRST: issue prefetch of tile t+2 into buffer (t+2)%3.
        //     That buffer was fully consumed at iteration t-1 (all lanes of this
        //     warp are past it), so no WAR and no syncwarp gate. DRAM issue
        //     stream never pauses on the convert chain below. ---
        if (t + 2 < NTILES) {
            const char* g = dbase + (size_t)(t + 2) * TILE_M * 512 + g_w_base;
            uint32_t sdst = smS + (uint32_t)((t + 2) % NSTG) * STAGE_B + s_w_base;
            #pragma unroll
            for (int r = 0; r < 8; r++)
                cp_async16(sdst + r * SPITCH, g + r * 512);
        }
        cp_commit();     // unconditional: uniform wait accounting

        cp_wait2();      // tile t's group retired (<=2 newer pending)
        __syncwarp();    // warp-wide visibility of warp's rows

        const uint32_t trd = smS + (uint32_t)(t % NSTG) * STAGE_B + s_r_base;

        // --- read fragment elements straight from f32 stage; convert in registers ---
        uint32_t af0[8], af1[8];
        float ss = 0.f;
        #pragma unroll
        for (int kb = 0; kb < 8; kb++) {
            float2 p0 = lds_v2(trd + kb * 64);
            float2 p1 = lds_v2(trd + kb * 64 + 32);
            ss += p0.x * p0.x + p0.y * p0.y + p1.x * p1.x + p1.y * p1.y;
            af0[kb] = pack_h2(p0.x, p0.y);
            af1[kb] = pack_h2(p1.x, p1.y);
        }
        // row norm: 4 lanes (same lane>>2) hold disjoint 32-col partials
        ss += __shfl_xor_sync(0xFFFFFFFFu, ss, 1);
        ss += __shfl_xor_sync(0xFFFFFFFFu, ss, 2);
        const float rn = rsqrtf(fmaxf(ss, 1e-24f));

        // --- HMMA: 8 real doc rows x 32 queries (upper fragment half duplicated) ---
        float acc[4][4];
        #pragma unroll
        for (int n = 0; n < 4; n++)
            #pragma unroll
            for (int i = 0; i < 4; i++) acc[n][i] = 0.f;

        #pragma unroll
        for (int kb = 0; kb < 8; kb++) {
            uint32_t aa[4] = {af0[kb], af0[kb], af1[kb], af1[kb]};
            #pragma unroll
            for (int n = 0; n < 4; n++) mma16816(acc[n], aa, bf[kb][n]);
        }

        // --- epilogue: c0,c1 are this thread's row; scale by 1/||d||, running max ---
        #pragma unroll
        for (int n = 0; n < 4; n++) {
            vmax[n * 2 + 0] = fmaxf(vmax[n * 2 + 0], acc[n][0] * rn);
            vmax[n * 2 + 1] = fmaxf(vmax[n * 2 + 1], acc[n][1] * rn);
        }
    }

    // ---- reduce: max over lanes sharing a query column (xor 4,8,16) ----
    #pragma unroll
    for (int e = 0; e < 8; e++) {
        vmax[e] = fmaxf(vmax[e], __shfl_xor_sync(0xFFFFFFFFu, vmax[e], 4));
        vmax[e] = fmaxf(vmax[e], __shfl_xor_sync(0xFFFFFFFFu, vmax[e], 8));
        vmax[e] = fmaxf(vmax[e], __shfl_xor_sync(0xFFFFFFFFu, vmax[e], 16));
    }
    if (lane < 4) {
        #pragma unroll
        for (int e = 0; e < 8; e++) {
            int col = (e >> 1) * 8 + lane * 2 + (e & 1);
            red[w * 32 + col] = vmax[e];
        }
    }
    __syncthreads();
    if (tid < 32) {
        float m = red[tid];
        #pragma unroll
        for (int ww = 1; ww < NW; ww++) m = fmaxf(m, red[ww * 32 + tid]);
        #pragma unroll
        for (int o = 16; o; o >>= 1) m += __shfl_xor_sync(0xFFFFFFFFu, m, o);
        if (tid == 0) out[b] = m;
    }
}

// ---------------- host launch ----------------
extern "C" void kernel_launch(void* const* d_in, const int* in_sizes, int n_in,
                              void* d_out, int out_size) {
    const float* q   = (const float*)d_in[0];   // [1024, 32, 128] f32
    const float* doc = (const float*)d_in[1];   // [1024, 2048, 128] f32
    float* out = (float*)d_out;                 // [1024] f32

    cudaFuncSetAttribute(maxsim_kernel,
                         cudaFuncAttributeMaxDynamicSharedMemorySize, SMEM_TOTAL);

    maxsim_kernel<<<NB, NT, SMEM_TOTAL>>>(q, doc, out);
}